// round 1
// baseline (speedup 1.0000x reference)
#include <cuda_runtime.h>
#include <cuda_bf16.h>

// Problem dims
#define NB 64
#define TT 512
#define II 512
#define HH 1024
#define OO 512
#define NT (NB*TT)        // 32768
#define NHh (NB*HH)       // 65536 floats per timestep slab

// ---------------- scratch (device globals; no cudaMalloc allowed) -------------
__device__ float g_bufA[TT*NB*HH];   // 128 MB : inp_v -> hs_v (in-place)
__device__ float g_bufB[TT*NB*HH];   // 128 MB : inp_m -> hs_m (in-place)
__device__ float g_bufO[NT*OO];      //  64 MB : out_v
__device__ float g_bufO2[NT*OO];     //  64 MB : out_t
__device__ unsigned g_count;         // grid barrier arrive counter (returns to 0)
__device__ unsigned g_epoch;         // grid barrier epoch (monotone across replays)

// ---------------- packed fp32x2 helpers (Blackwell dual-FP32 pipe) ------------
__device__ __forceinline__ unsigned long long dup2(float a) {
    unsigned long long r;
    asm("mov.b64 %0, {%1, %1};" : "=l"(r) : "f"(a));
    return r;
}
__device__ __forceinline__ void fma2(unsigned long long& c, unsigned long long a,
                                     unsigned long long b) {
    asm("fma.rn.f32x2 %0, %1, %2, %0;" : "+l"(c) : "l"(a), "l"(b));
}
__device__ __forceinline__ float lo32(unsigned long long v) {
    return __uint_as_float((unsigned)(v & 0xffffffffull));
}
__device__ __forceinline__ float hi32(unsigned long long v) {
    return __uint_as_float((unsigned)(v >> 32));
}
__device__ __forceinline__ unsigned ldvol(const unsigned* p) {
    unsigned v;
    asm volatile("ld.global.cg.u32 %0, [%1];" : "=r"(v) : "l"(p));
    return v;
}
__device__ __forceinline__ float retanh(float x) { return tanhf(fmaxf(x, 0.0f)); }

// ======================= SGEMM: C[remap(m)][:] = A[m,:K] @ B[:,K]^T + bias ====
// A: [M,K] row-major (contiguous). B: [Nc,K] row-major (weights).
// Output row = (m % D1) * D2 + (m / D1)   (handles NT<->TN layout transposes).
#define BM 128
#define BN 128
#define BK 16

__global__ __launch_bounds__(256) void sgemm_kernel(
    const float* __restrict__ A, const float* __restrict__ B,
    const float* __restrict__ bias1, const float* __restrict__ bias2,
    float* __restrict__ C, int M, int Nc, int K, int D1, int D2, int act)
{
    __shared__ float As[BK][BM + 8];   // stride 136 floats (544B, 16B-aligned)
    __shared__ float Bs[BK][BN + 8];

    const int tid = threadIdx.x;
    const int m0 = blockIdx.y * BM;
    const int j0 = blockIdx.x * BN;
    const int tm = tid >> 4;          // 0..15
    const int tn = tid & 15;          // 0..15
    const int lr = tid >> 2;          // 0..63
    const int lk = (tid & 3) * 4;     // 0,4,8,12

    unsigned long long acc[8][4];
#pragma unroll
    for (int i = 0; i < 8; i++)
#pragma unroll
        for (int j = 0; j < 4; j++) acc[i][j] = 0ull;

    for (int kt = 0; kt < K; kt += BK) {
#pragma unroll
        for (int rr = 0; rr < 2; rr++) {
            const int r = lr + rr * 64;
            float4 va = *(const float4*)(A + (size_t)(m0 + r) * K + kt + lk);
            As[lk + 0][r] = va.x; As[lk + 1][r] = va.y;
            As[lk + 2][r] = va.z; As[lk + 3][r] = va.w;
            float4 vb = *(const float4*)(B + (size_t)(j0 + r) * K + kt + lk);
            Bs[lk + 0][r] = vb.x; Bs[lk + 1][r] = vb.y;
            Bs[lk + 2][r] = vb.z; Bs[lk + 3][r] = vb.w;
        }
        __syncthreads();

#pragma unroll
        for (int kk = 0; kk < BK; kk++) {
            float a[8];
            *(float4*)&a[0] = *(const float4*)&As[kk][tm * 8];
            *(float4*)&a[4] = *(const float4*)&As[kk][tm * 8 + 4];
            ulonglong2 b01 = *(const ulonglong2*)&Bs[kk][tn * 8];
            ulonglong2 b23 = *(const ulonglong2*)&Bs[kk][tn * 8 + 4];
#pragma unroll
            for (int i = 0; i < 8; i++) {
                unsigned long long ad = dup2(a[i]);
                fma2(acc[i][0], ad, b01.x);
                fma2(acc[i][1], ad, b01.y);
                fma2(acc[i][2], ad, b23.x);
                fma2(acc[i][3], ad, b23.y);
            }
        }
        __syncthreads();
    }

    // epilogue: bias (+bias2), optional retanh, row remap
    float bcol[8];
#pragma unroll
    for (int j = 0; j < 8; j++) {
        const int cn = j0 + tn * 8 + j;
        float b = bias1[cn];
        if (bias2) b += bias2[cn];
        bcol[j] = b;
    }
#pragma unroll
    for (int i = 0; i < 8; i++) {
        const int rm = m0 + tm * 8 + i;
        const int orow = (rm % D1) * D2 + (rm / D1);
        float out[8];
#pragma unroll
        for (int j = 0; j < 4; j++) {
            out[2 * j + 0] = lo32(acc[i][j]) + bcol[2 * j + 0];
            out[2 * j + 1] = hi32(acc[i][j]) + bcol[2 * j + 1];
        }
        if (act) {
#pragma unroll
            for (int j = 0; j < 8; j++) out[j] = retanh(out[j]);
        }
        float* cp = C + (size_t)orow * Nc + j0 + tn * 8;
        *(float4*)cp       = *(float4*)&out[0];
        *(float4*)(cp + 4) = *(float4*)&out[4];
    }
}

// ======================= Persistent recurrence kernel =========================
// buf: [T, N, H] pre-activations (x_t + bi + bh, folded upstream);
// overwritten in place with h_t. Grid = 128 CTAs (2 batch halves x 64 col-slices
// of 16). Wh slice (16x1024) resident in SMEM (k-major for f32x2 column pairs).
// K split 4-way across warps, SMEM reduce, epoch grid barrier per step.
#define RGRID 128
#define RTHR  512
#define RSMEM (16*1024*4 + 4*32*16*4)   // Whs 64KB + red 8KB = 73728

__global__ __launch_bounds__(RTHR) void recur_kernel(
    float* __restrict__ buf, const float* __restrict__ Wh,
    const float* __restrict__ h0)
{
    extern __shared__ float smem[];
    float* Whs = smem;                  // [1024][16]  Whs[k][cl] = Wh[c0+cl][k]
    float* red = smem + 1024 * 16;      // [4][32][16]

    const int tid  = threadIdx.x;
    const int bidb = blockIdx.x >> 6;   // 0..1  batch half
    const int bidh = blockIdx.x & 63;   // 0..63 column slice
    const int nb0  = bidb * 32;
    const int c0   = bidh * 16;

    unsigned eps = 0;
    if (tid == 0) eps = ldvol(&g_epoch);   // before any arrive: launch-stable

    // load Wh slice transposed into SMEM (once)
    {
        const int cl = tid & 15;
        const int kb = (tid >> 4) * 32;
        const float* wrow = Wh + (size_t)(c0 + cl) * HH + kb;
#pragma unroll
        for (int kk = 0; kk < 32; kk++) Whs[(kb + kk) * 16 + cl] = wrow[kk];
    }
    __syncthreads();

    const int wid  = tid >> 5;
    const int lane = tid & 31;
    const int cc   = (wid & 3) * 4;     // 4 columns per warp
    const int k0   = (wid >> 2) * 256;  // 256-k chunk per warp
    const int rr   = tid >> 4;          // reduce: row 0..31
    const int rc   = tid & 15;          // reduce: col 0..15

    for (int t = 0; t < TT; t++) {
        const float4* hrow = (const float4*)(
            (t == 0 ? h0 : buf + (size_t)(t - 1) * NHh)
            + (size_t)(nb0 + lane) * HH + k0);

        unsigned long long acc01 = 0ull, acc23 = 0ull;
#pragma unroll 8
        for (int i = 0; i < 64; i++) {
            const float4 hv = __ldcg(hrow + i);
            const int kb = (k0 + i * 4) * 16 + cc;
            {
                unsigned long long ad = dup2(hv.x);
                ulonglong2 wv = *(const ulonglong2*)&Whs[kb];
                fma2(acc01, ad, wv.x); fma2(acc23, ad, wv.y);
            }
            {
                unsigned long long ad = dup2(hv.y);
                ulonglong2 wv = *(const ulonglong2*)&Whs[kb + 16];
                fma2(acc01, ad, wv.x); fma2(acc23, ad, wv.y);
            }
            {
                unsigned long long ad = dup2(hv.z);
                ulonglong2 wv = *(const ulonglong2*)&Whs[kb + 32];
                fma2(acc01, ad, wv.x); fma2(acc23, ad, wv.y);
            }
            {
                unsigned long long ad = dup2(hv.w);
                ulonglong2 wv = *(const ulonglong2*)&Whs[kb + 48];
                fma2(acc01, ad, wv.x); fma2(acc23, ad, wv.y);
            }
        }
        // partials -> red[kg][lane][cc..cc+3]
        float4 p;
        p.x = lo32(acc01); p.y = hi32(acc01);
        p.z = lo32(acc23); p.w = hi32(acc23);
        *(float4*)&red[(((wid >> 2) * 32 + lane) * 16) + cc] = p;
        __syncthreads();

        // reduce 4 k-chunks, add pre-activation, retanh, write h_t
        float s = red[(0 * 32 + rr) * 16 + rc] + red[(1 * 32 + rr) * 16 + rc]
                + red[(2 * 32 + rr) * 16 + rc] + red[(3 * 32 + rr) * 16 + rc];
        float* outp = buf + (size_t)t * NHh + (size_t)(nb0 + rr) * HH + (c0 + rc);
        float v = s + __ldcg(outp);
        *outp = retanh(v);

        // ---- grid barrier (epoch-based, replay-safe, wrap-safe) ----
        __syncthreads();
        if (tid == 0) {
            __threadfence();
            const unsigned a = atomicAdd(&g_count, 1u);
            if (a == RGRID - 1) {
                atomicExch(&g_count, 0u);
                __threadfence();
                atomicAdd(&g_epoch, 1u);
            } else {
                const unsigned tgt = (unsigned)(t + 1);
                while (ldvol(&g_epoch) - eps < tgt) { __nanosleep(64); }
            }
            __threadfence();
        }
        __syncthreads();
    }
}

// ======================= launcher ==============================================
static void launch_gemm(const float* A, const float* B, const float* b1,
                        const float* b2, float* C, int M, int Nc, int K,
                        int D1, int D2, int act)
{
    dim3 grid(Nc / BN, M / BM);
    sgemm_kernel<<<grid, 256>>>(A, B, b1, b2, C, M, Nc, K, D1, D2, act);
}

extern "C" void kernel_launch(void* const* d_in, const int* in_sizes, int n_in,
                              void* d_out, int out_size)
{
    const float* data = (const float*)d_in[0];   // [N,T,I]
    const float* h0_v = (const float*)d_in[1];
    const float* h0_m = (const float*)d_in[2];
    const float* Wi   = (const float*)d_in[3];
    const float* bi   = (const float*)d_in[4];
    const float* Wh   = (const float*)d_in[5];
    const float* bh   = (const float*)d_in[6];
    const float* Wo   = (const float*)d_in[7];
    const float* bo   = (const float*)d_in[8];
    const float* Wt   = (const float*)d_in[9];
    const float* bt   = (const float*)d_in[10];
    const float* Wi2  = (const float*)d_in[11];
    const float* bi2  = (const float*)d_in[12];
    const float* Wh2  = (const float*)d_in[13];
    const float* bh2  = (const float*)d_in[14];
    const float* Wo2  = (const float*)d_in[15];
    const float* bo2  = (const float*)d_in[16];
    float* out = (float*)d_out;

    float *bufA, *bufB, *bufO, *bufO2;
    cudaGetSymbolAddress((void**)&bufA,  g_bufA);
    cudaGetSymbolAddress((void**)&bufB,  g_bufB);
    cudaGetSymbolAddress((void**)&bufO,  g_bufO);
    cudaGetSymbolAddress((void**)&bufO2, g_bufO2);

    cudaFuncSetAttribute(recur_kernel,
                         cudaFuncAttributeMaxDynamicSharedMemorySize, RSMEM);

    // 1) inp_v = data @ Wi^T + (bi + bh), [N*T] rows -> [T,N,H]
    launch_gemm(data, Wi, bi, bh, bufA, NT, HH, II, TT, NB, 0);
    // 2) visual recurrence (in-place on bufA)
    recur_kernel<<<RGRID, RTHR, RSMEM>>>(bufA, Wh, h0_v);
    // 3) out_v = hs_v @ Wo^T + bo, [T,N,H] -> [N,T,O]
    launch_gemm(bufA, Wo, bo, nullptr, bufO, NT, OO, HH, NB, TT, 0);
    // 4) out_t = retanh(out_v @ Wt^T + bt), identity layout
    launch_gemm(bufO, Wt, bt, nullptr, bufO2, NT, OO, OO, NT, 1, 1);
    // 5) inp_m = out_t @ Wi2^T + (bi2 + bh2), [N,T,O] -> [T,N,H]
    launch_gemm(bufO2, Wi2, bi2, bh2, bufB, NT, HH, OO, TT, NB, 0);
    // 6) motor recurrence (in-place on bufB)
    recur_kernel<<<RGRID, RTHR, RSMEM>>>(bufB, Wh2, h0_m);
    // 7) out_m = hs_m @ Wo2^T + bo2, [T,N,H] -> [N,T,O] into d_out
    launch_gemm(bufB, Wo2, bo2, nullptr, out, NT, OO, HH, NB, TT, 0);
}

// round 2
// speedup vs baseline: 3.0572x; 3.0572x over previous
#include <cuda_runtime.h>
#include <cuda_bf16.h>

// Problem dims
#define NB 64
#define TT 512
#define II 512
#define HH 1024
#define OO 512
#define NT (NB*TT)        // 32768
#define NHh (NB*HH)       // 65536 floats per timestep slab

// ---------------- scratch (device globals; no cudaMalloc allowed) -------------
__device__ float g_bufA[TT*NB*HH];   // 128 MB : inp_v -> hs_v (in-place)
__device__ float g_bufB[TT*NB*HH];   // 128 MB : inp_m -> hs_m (in-place)
__device__ float g_bufO[NT*OO];      //  64 MB : out_v
__device__ float g_bufO2[NT*OO];     //  64 MB : out_t
__device__ float g_hx0[HH*NB];       // ping-pong h exchange, [H][N] layout
__device__ float g_hx1[HH*NB];
__device__ unsigned g_count;         // grid barrier arrive counter (returns to 0)
__device__ unsigned g_epoch;         // grid barrier epoch (monotone across replays)

// ---------------- packed fp32x2 helpers (Blackwell dual-FP32 pipe) ------------
__device__ __forceinline__ unsigned long long dup2(float a) {
    unsigned long long r;
    asm("mov.b64 %0, {%1, %1};" : "=l"(r) : "f"(a));
    return r;
}
__device__ __forceinline__ void fma2(unsigned long long& c, unsigned long long a,
                                     unsigned long long b) {
    asm("fma.rn.f32x2 %0, %1, %2, %0;" : "+l"(c) : "l"(a), "l"(b));
}
__device__ __forceinline__ float lo32(unsigned long long v) {
    return __uint_as_float((unsigned)(v & 0xffffffffull));
}
__device__ __forceinline__ float hi32(unsigned long long v) {
    return __uint_as_float((unsigned)(v >> 32));
}
__device__ __forceinline__ unsigned ld_relaxed(const unsigned* p) {
    unsigned v;
    asm volatile("ld.global.relaxed.gpu.u32 %0, [%1];" : "=r"(v) : "l"(p));
    return v;
}
__device__ __forceinline__ unsigned ld_acquire(const unsigned* p) {
    unsigned v;
    asm volatile("ld.acquire.gpu.global.u32 %0, [%1];" : "=r"(v) : "l"(p));
    return v;
}
__device__ __forceinline__ unsigned atom_add_release(unsigned* p, unsigned v) {
    unsigned old;
    asm volatile("atom.add.release.gpu.global.u32 %0, [%1], %2;"
                 : "=r"(old) : "l"(p), "r"(v));
    return old;
}
__device__ __forceinline__ void red_add_release(unsigned* p, unsigned v) {
    asm volatile("red.add.release.gpu.global.u32 [%0], %1;" :: "l"(p), "r"(v));
}
__device__ __forceinline__ float retanh(float x) { return tanhf(fmaxf(x, 0.0f)); }

// ======================= SGEMM: C[remap(m)][:] = A[m,:K] @ B[:,K]^T + bias ====
#define BM 128
#define BN 128
#define BK 16

__global__ __launch_bounds__(256) void sgemm_kernel(
    const float* __restrict__ A, const float* __restrict__ B,
    const float* __restrict__ bias1, const float* __restrict__ bias2,
    float* __restrict__ C, int M, int Nc, int K, int D1, int D2, int act)
{
    __shared__ float As[BK][BM + 8];
    __shared__ float Bs[BK][BN + 8];

    const int tid = threadIdx.x;
    const int m0 = blockIdx.y * BM;
    const int j0 = blockIdx.x * BN;
    const int tm = tid >> 4;
    const int tn = tid & 15;
    const int lr = tid >> 2;
    const int lk = (tid & 3) * 4;

    unsigned long long acc[8][4];
#pragma unroll
    for (int i = 0; i < 8; i++)
#pragma unroll
        for (int j = 0; j < 4; j++) acc[i][j] = 0ull;

    for (int kt = 0; kt < K; kt += BK) {
#pragma unroll
        for (int rr = 0; rr < 2; rr++) {
            const int r = lr + rr * 64;
            float4 va = *(const float4*)(A + (size_t)(m0 + r) * K + kt + lk);
            As[lk + 0][r] = va.x; As[lk + 1][r] = va.y;
            As[lk + 2][r] = va.z; As[lk + 3][r] = va.w;
            float4 vb = *(const float4*)(B + (size_t)(j0 + r) * K + kt + lk);
            Bs[lk + 0][r] = vb.x; Bs[lk + 1][r] = vb.y;
            Bs[lk + 2][r] = vb.z; Bs[lk + 3][r] = vb.w;
        }
        __syncthreads();

#pragma unroll
        for (int kk = 0; kk < BK; kk++) {
            float a[8];
            *(float4*)&a[0] = *(const float4*)&As[kk][tm * 8];
            *(float4*)&a[4] = *(const float4*)&As[kk][tm * 8 + 4];
            ulonglong2 b01 = *(const ulonglong2*)&Bs[kk][tn * 8];
            ulonglong2 b23 = *(const ulonglong2*)&Bs[kk][tn * 8 + 4];
#pragma unroll
            for (int i = 0; i < 8; i++) {
                unsigned long long ad = dup2(a[i]);
                fma2(acc[i][0], ad, b01.x);
                fma2(acc[i][1], ad, b01.y);
                fma2(acc[i][2], ad, b23.x);
                fma2(acc[i][3], ad, b23.y);
            }
        }
        __syncthreads();
    }

    float bcol[8];
#pragma unroll
    for (int j = 0; j < 8; j++) {
        const int cn = j0 + tn * 8 + j;
        float b = bias1[cn];
        if (bias2) b += bias2[cn];
        bcol[j] = b;
    }
#pragma unroll
    for (int i = 0; i < 8; i++) {
        const int rm = m0 + tm * 8 + i;
        const int orow = (rm % D1) * D2 + (rm / D1);
        float out[8];
#pragma unroll
        for (int j = 0; j < 4; j++) {
            out[2 * j + 0] = lo32(acc[i][j]) + bcol[2 * j + 0];
            out[2 * j + 1] = hi32(acc[i][j]) + bcol[2 * j + 1];
        }
        if (act) {
#pragma unroll
            for (int j = 0; j < 8; j++) out[j] = retanh(out[j]);
        }
        float* cp = C + (size_t)orow * Nc + j0 + tn * 8;
        *(float4*)cp       = *(float4*)&out[0];
        *(float4*)(cp + 4) = *(float4*)&out[4];
    }
}

// ======================= h0 transpose: [N,H] -> [H,N] ========================
__global__ __launch_bounds__(512) void transpose_h0(
    const float* __restrict__ h0, float* __restrict__ hx)
{
    const int idx = blockIdx.x * 512 + threadIdx.x;   // 0..65535
    const int h = idx >> 6, n = idx & 63;
    hx[idx] = h0[(size_t)n * HH + h];
}

// ======================= Persistent recurrence kernel =========================
// buf: [T, N, H] pre-activations (x_t + bi + bh); overwritten in place with h_t.
// Cross-step h exchange through hx0/hx1 in [H][N] layout (coalesced).
// Grid = 128 CTAs = 2 batch halves x 64 column-slices of 16.
// 16 warps each own a 64-wide k-chunk and compute all 16 columns (f32x2).
#define RGRID 128
#define RTHR  512
// Whs: 1024*16 floats (64KB) + redU: 16*32*9 ull (36KB)
#define RSMEM (16*1024*4 + 16*32*9*8)

__global__ __launch_bounds__(RTHR) void recur_kernel(
    float* __restrict__ buf, const float* __restrict__ Wh,
    float* __restrict__ hx0, float* __restrict__ hx1)
{
    extern __shared__ float smem[];
    float* Whs = smem;                                   // [1024][16]
    unsigned long long* redU = (unsigned long long*)(smem + 1024 * 16); // [16][32][9]

    const int tid  = threadIdx.x;
    const int bidb = blockIdx.x >> 6;   // batch half
    const int bidh = blockIdx.x & 63;   // column slice
    const int nb0  = bidb * 32;
    const int c0   = bidh * 16;

    unsigned eps = 0;
    if (tid == 0) eps = ld_relaxed(&g_epoch);

    // Wh slice transposed into SMEM: Whs[k][cl] = Wh[c0+cl][k]
    {
        const int cl = tid & 15;
        const int kb = (tid >> 4) * 32;
        const float* wrow = Wh + (size_t)(c0 + cl) * HH + kb;
#pragma unroll
        for (int kk = 0; kk < 32; kk++) Whs[(kb + kk) * 16 + cl] = wrow[kk];
    }
    __syncthreads();

    const int wid  = tid >> 5;          // k-chunk 0..15
    const int lane = tid & 31;          // batch row within half
    const int k0   = wid * 64;
    const int rr   = tid >> 4;          // reduce: n 0..31
    const int rc   = tid & 15;          // reduce: c 0..15
    const float* redF = (const float*)redU;

    for (int t = 0; t < TT; t++) {
        const float* hp = ((t & 1) ? hx1 : hx0) + (size_t)k0 * NB + nb0 + lane;
        float*       hn = ((t & 1) ? hx0 : hx1);

        unsigned long long acc[8];
#pragma unroll
        for (int j = 0; j < 8; j++) acc[j] = 0ull;

#pragma unroll 8
        for (int i = 0; i < 64; i++) {
            const float hv = __ldcg(hp + (size_t)i * NB);
            const unsigned long long ad = dup2(hv);
            const float* wk = &Whs[(k0 + i) * 16];
            ulonglong2 w0 = *(const ulonglong2*)(wk + 0);
            ulonglong2 w1 = *(const ulonglong2*)(wk + 4);
            ulonglong2 w2 = *(const ulonglong2*)(wk + 8);
            ulonglong2 w3 = *(const ulonglong2*)(wk + 12);
            fma2(acc[0], ad, w0.x); fma2(acc[1], ad, w0.y);
            fma2(acc[2], ad, w1.x); fma2(acc[3], ad, w1.y);
            fma2(acc[4], ad, w2.x); fma2(acc[5], ad, w2.y);
            fma2(acc[6], ad, w3.x); fma2(acc[7], ad, w3.y);
        }

        // partials -> redU[wid][lane][0..7] (stride 9 ull => <=2-way conflicts)
        {
            unsigned long long* rp = &redU[(size_t)(wid * 32 + lane) * 9];
#pragma unroll
            for (int j = 0; j < 8; j++) rp[j] = acc[j];
        }
        __syncthreads();

        // reduce 16 k-chunks for output (n=rr, c=rc)
        float s = 0.0f;
#pragma unroll
        for (int w = 0; w < 16; w++) {
            s += redF[((w * 32 + rr) * 9 + (rc >> 1)) * 2 + (rc & 1)];
        }
        float* outp = buf + (size_t)t * NHh + (size_t)(nb0 + rr) * HH + (c0 + rc);
        const float v = retanh(s + __ldcg(outp));
        *outp = v;                                      // for downstream GEMM
        hn[(size_t)(c0 + rc) * NB + nb0 + rr] = v;      // for next step

        // ---- grid barrier (release/acquire, no L1 flush) ----
        __syncthreads();
        if (tid == 0) {
            const unsigned a = atom_add_release(&g_count, 1u);
            if (a == RGRID - 1) {
                atomicExch(&g_count, 0u);
                red_add_release(&g_epoch, 1u);
            } else {
                const unsigned tgt = (unsigned)(t + 1);
                while (ld_acquire(&g_epoch) - eps < tgt) { __nanosleep(32); }
            }
        }
        __syncthreads();
    }
}

// ======================= launcher ==============================================
static void launch_gemm(const float* A, const float* B, const float* b1,
                        const float* b2, float* C, int M, int Nc, int K,
                        int D1, int D2, int act)
{
    dim3 grid(Nc / BN, M / BM);
    sgemm_kernel<<<grid, 256>>>(A, B, b1, b2, C, M, Nc, K, D1, D2, act);
}

extern "C" void kernel_launch(void* const* d_in, const int* in_sizes, int n_in,
                              void* d_out, int out_size)
{
    const float* data = (const float*)d_in[0];
    const float* h0_v = (const float*)d_in[1];
    const float* h0_m = (const float*)d_in[2];
    const float* Wi   = (const float*)d_in[3];
    const float* bi   = (const float*)d_in[4];
    const float* Wh   = (const float*)d_in[5];
    const float* bh   = (const float*)d_in[6];
    const float* Wo   = (const float*)d_in[7];
    const float* bo   = (const float*)d_in[8];
    const float* Wt   = (const float*)d_in[9];
    const float* bt   = (const float*)d_in[10];
    const float* Wi2  = (const float*)d_in[11];
    const float* bi2  = (const float*)d_in[12];
    const float* Wh2  = (const float*)d_in[13];
    const float* bh2  = (const float*)d_in[14];
    const float* Wo2  = (const float*)d_in[15];
    const float* bo2  = (const float*)d_in[16];
    float* out = (float*)d_out;

    float *bufA, *bufB, *bufO, *bufO2, *hx0, *hx1;
    cudaGetSymbolAddress((void**)&bufA,  g_bufA);
    cudaGetSymbolAddress((void**)&bufB,  g_bufB);
    cudaGetSymbolAddress((void**)&bufO,  g_bufO);
    cudaGetSymbolAddress((void**)&bufO2, g_bufO2);
    cudaGetSymbolAddress((void**)&hx0,   g_hx0);
    cudaGetSymbolAddress((void**)&hx1,   g_hx1);

    cudaFuncSetAttribute(recur_kernel,
                         cudaFuncAttributeMaxDynamicSharedMemorySize, RSMEM);

    // 1) inp_v = data @ Wi^T + (bi + bh) -> [T,N,H]
    launch_gemm(data, Wi, bi, bh, bufA, NT, HH, II, TT, NB, 0);
    // 2) visual recurrence
    transpose_h0<<<128, 512>>>(h0_v, hx0);
    recur_kernel<<<RGRID, RTHR, RSMEM>>>(bufA, Wh, hx0, hx1);
    // 3) out_v = hs_v @ Wo^T + bo -> [N,T,O]
    launch_gemm(bufA, Wo, bo, nullptr, bufO, NT, OO, HH, NB, TT, 0);
    // 4) out_t = retanh(out_v @ Wt^T + bt)
    launch_gemm(bufO, Wt, bt, nullptr, bufO2, NT, OO, OO, NT, 1, 1);
    // 5) inp_m = out_t @ Wi2^T + (bi2 + bh2) -> [T,N,H]
    launch_gemm(bufO2, Wi2, bi2, bh2, bufB, NT, HH, OO, TT, NB, 0);
    // 6) motor recurrence
    transpose_h0<<<128, 512>>>(h0_m, hx0);
    recur_kernel<<<RGRID, RTHR, RSMEM>>>(bufB, Wh2, hx0, hx1);
    // 7) out_m = hs_m @ Wo2^T + bo2 -> [N,T,O]
    launch_gemm(bufB, Wo2, bo2, nullptr, out, NT, OO, HH, NB, TT, 0);
}

// round 4
// speedup vs baseline: 3.2816x; 1.0734x over previous
#include <cuda_runtime.h>
#include <cuda_bf16.h>

// Problem dims
#define NB 64
#define TT 512
#define II 512
#define HH 1024
#define OO 512
#define NT (NB*TT)        // 32768
#define NHh (NB*HH)       // 65536 floats per timestep slab

// ---------------- scratch (device globals; no cudaMalloc allowed) -------------
__device__ float g_bufA[TT*NB*HH];   // 128 MB : inp_v -> hs_v (in-place)
__device__ float g_bufB[TT*NB*HH];   // 128 MB : inp_m -> hs_m (in-place)
__device__ float g_bufO[NT*OO];      //  64 MB : out_v
__device__ float g_bufO2[NT*OO];     //  64 MB : out_t
__device__ float g_hx0[HH*NB];       // ping-pong h exchange, [H][N] layout
__device__ float g_hx1[HH*NB];
// two-level barrier state: 8 group counters + 2 half-epoch counters, padded
__device__ unsigned g_grpc[8*32];
__device__ unsigned g_epc[2*32];

// ---------------- packed fp32x2 helpers (Blackwell dual-FP32 pipe) ------------
__device__ __forceinline__ unsigned long long dup2(float a) {
    unsigned long long r;
    asm("mov.b64 %0, {%1, %1};" : "=l"(r) : "f"(a));
    return r;
}
__device__ __forceinline__ void fma2(unsigned long long& c, unsigned long long a,
                                     unsigned long long b) {
    asm("fma.rn.f32x2 %0, %1, %2, %0;" : "+l"(c) : "l"(a), "l"(b));
}
__device__ __forceinline__ float lo32(unsigned long long v) {
    return __uint_as_float((unsigned)(v & 0xffffffffull));
}
__device__ __forceinline__ float hi32(unsigned long long v) {
    return __uint_as_float((unsigned)(v >> 32));
}
__device__ __forceinline__ unsigned ld_acquire(const unsigned* p) {
    unsigned v;
    asm volatile("ld.acquire.gpu.global.u32 %0, [%1];" : "=r"(v) : "l"(p));
    return v;
}
__device__ __forceinline__ unsigned atom_add_acqrel(unsigned* p, unsigned v) {
    unsigned old;
    asm volatile("atom.add.acq_rel.gpu.global.u32 %0, [%1], %2;"
                 : "=r"(old) : "l"(p), "r"(v));
    return old;
}
__device__ __forceinline__ void red_add_release(unsigned* p, unsigned v) {
    asm volatile("red.add.release.gpu.global.u32 [%0], %1;" :: "l"(p), "r"(v));
}
__device__ __forceinline__ float retanh(float x) { return tanhf(fmaxf(x, 0.0f)); }

// ======================= SGEMM: C[remap(m)][:] = A[m,:K] @ B[:,K]^T + bias ====
// Register-prefetch pipelined: next tile's LDGs overlap current tile's FMAs.
#define BM 128
#define BN 128
#define BK 16

__global__ __launch_bounds__(256, 2) void sgemm_kernel(
    const float* __restrict__ A, const float* __restrict__ B,
    const float* __restrict__ bias1, const float* __restrict__ bias2,
    float* __restrict__ C, int M, int Nc, int K, int D1, int D2, int act)
{
    __shared__ float As[BK][BM + 8];
    __shared__ float Bs[BK][BN + 8];

    const int tid = threadIdx.x;
    const int m0 = blockIdx.y * BM;
    const int j0 = blockIdx.x * BN;
    const int tm = tid >> 4;
    const int tn = tid & 15;
    const int lr = tid >> 2;
    const int lk = (tid & 3) * 4;

    const float* ap0 = A + (size_t)(m0 + lr) * K + lk;
    const float* ap1 = A + (size_t)(m0 + lr + 64) * K + lk;
    const float* bp0 = B + (size_t)(j0 + lr) * K + lk;
    const float* bp1 = B + (size_t)(j0 + lr + 64) * K + lk;

    unsigned long long acc[8][4];
#pragma unroll
    for (int i = 0; i < 8; i++)
#pragma unroll
        for (int j = 0; j < 4; j++) acc[i][j] = 0ull;

    // preload tile 0 into registers
    float4 pa0 = *(const float4*)ap0;
    float4 pa1 = *(const float4*)ap1;
    float4 pb0 = *(const float4*)bp0;
    float4 pb1 = *(const float4*)bp1;

    for (int kt = 0; kt < K; kt += BK) {
        // stage prefetched tile into SMEM
        As[lk + 0][lr] = pa0.x; As[lk + 1][lr] = pa0.y;
        As[lk + 2][lr] = pa0.z; As[lk + 3][lr] = pa0.w;
        As[lk + 0][lr + 64] = pa1.x; As[lk + 1][lr + 64] = pa1.y;
        As[lk + 2][lr + 64] = pa1.z; As[lk + 3][lr + 64] = pa1.w;
        Bs[lk + 0][lr] = pb0.x; Bs[lk + 1][lr] = pb0.y;
        Bs[lk + 2][lr] = pb0.z; Bs[lk + 3][lr] = pb0.w;
        Bs[lk + 0][lr + 64] = pb1.x; Bs[lk + 1][lr + 64] = pb1.y;
        Bs[lk + 2][lr + 64] = pb1.z; Bs[lk + 3][lr + 64] = pb1.w;
        __syncthreads();

        if (kt + BK < K) {   // next tile's LDGs fly during compute
            pa0 = *(const float4*)(ap0 + kt + BK);
            pa1 = *(const float4*)(ap1 + kt + BK);
            pb0 = *(const float4*)(bp0 + kt + BK);
            pb1 = *(const float4*)(bp1 + kt + BK);
        }

#pragma unroll
        for (int kk = 0; kk < BK; kk++) {
            float a[8];
            *(float4*)&a[0] = *(const float4*)&As[kk][tm * 8];
            *(float4*)&a[4] = *(const float4*)&As[kk][tm * 8 + 4];
            ulonglong2 b01 = *(const ulonglong2*)&Bs[kk][tn * 8];
            ulonglong2 b23 = *(const ulonglong2*)&Bs[kk][tn * 8 + 4];
#pragma unroll
            for (int i = 0; i < 8; i++) {
                unsigned long long ad = dup2(a[i]);
                fma2(acc[i][0], ad, b01.x);
                fma2(acc[i][1], ad, b01.y);
                fma2(acc[i][2], ad, b23.x);
                fma2(acc[i][3], ad, b23.y);
            }
        }
        __syncthreads();
    }

    float bcol[8];
#pragma unroll
    for (int j = 0; j < 8; j++) {
        const int cn = j0 + tn * 8 + j;
        float b = bias1[cn];
        if (bias2) b += bias2[cn];
        bcol[j] = b;
    }
#pragma unroll
    for (int i = 0; i < 8; i++) {
        const int rm = m0 + tm * 8 + i;
        const int orow = (rm % D1) * D2 + (rm / D1);
        float out[8];
#pragma unroll
        for (int j = 0; j < 4; j++) {
            out[2 * j + 0] = lo32(acc[i][j]) + bcol[2 * j + 0];
            out[2 * j + 1] = hi32(acc[i][j]) + bcol[2 * j + 1];
        }
        if (act) {
#pragma unroll
            for (int j = 0; j < 8; j++) out[j] = retanh(out[j]);
        }
        float* cp = C + (size_t)orow * Nc + j0 + tn * 8;
        *(float4*)cp       = *(float4*)&out[0];
        *(float4*)(cp + 4) = *(float4*)&out[4];
    }
}

// ======================= h0 transpose + barrier reset ========================
__global__ __launch_bounds__(512) void transpose_h0(
    const float* __restrict__ h0, float* __restrict__ hx)
{
    const int idx = blockIdx.x * 512 + threadIdx.x;
    const int h = idx >> 6, n = idx & 63;
    hx[idx] = h0[(size_t)n * HH + h];
}

__global__ void reset_barrier_kernel() {
    const int i = threadIdx.x;
    if (i < 8 * 32) g_grpc[i] = 0u;
    if (i < 2 * 32) g_epc[i] = 0u;
}

// ======================= Persistent recurrence kernel =========================
// Grid = 128 CTAs = 2 batch halves x 64 column-slices of 16.
// 16 warps each own a 64-wide k-chunk, compute all 16 columns via f32x2.
// Two-level per-half grid barrier (counters zeroed pre-launch; absolute targets).
#define RGRID 128
#define RTHR  512
// Whs 1024*16 f (64KB) + redU 4608 ull = 9216 f (36KB) + sv 16*33 f (2112B)
#define RSMEM ((16384 + 9216 + 528) * 4)

__global__ __launch_bounds__(RTHR) void recur_kernel(
    float* __restrict__ buf, const float* __restrict__ Wh,
    float* __restrict__ hx0, float* __restrict__ hx1)
{
    extern __shared__ float smem[];
    float* Whs = smem;                                                // [1024][16]
    unsigned long long* redU = (unsigned long long*)(smem + 16384);   // [16][32][9] ull
    float* sv = smem + 16384 + 9216;                                  // [16][33]

    const int tid  = threadIdx.x;
    const int bidb = blockIdx.x >> 6;     // batch half
    const int bidh = blockIdx.x & 63;     // column slice
    const int gid  = blockIdx.x >> 4;     // barrier group 0..7
    const int nb0  = bidb * 32;
    const int c0   = bidh * 16;

    // Wh slice transposed into SMEM: Whs[k][cl] = Wh[c0+cl][k]
    {
        const int cl = tid & 15;
        const int kb = (tid >> 4) * 32;
        const float* wrow = Wh + (size_t)(c0 + cl) * HH + kb;
#pragma unroll
        for (int kk = 0; kk < 32; kk++) Whs[(kb + kk) * 16 + cl] = wrow[kk];
    }
    __syncthreads();

    const int wid  = tid >> 5;            // k-chunk 0..15
    const int lane = tid & 31;            // batch row within half
    const int k0   = wid * 64;
    const int rr   = tid >> 4;            // reduce: n 0..31
    const int rc   = tid & 15;            // reduce: c 0..15
    const int c2   = tid >> 5;            // publish: c 0..15
    const int n2   = tid & 31;            // publish: n 0..31
    const float* redF = (const float*)redU;

    for (int t = 0; t < TT; t++) {
        const float* hp = ((t & 1) ? hx1 : hx0) + (size_t)k0 * NB + nb0 + lane;
        float*       hn = ((t & 1) ? hx0 : hx1);
        float* outp = buf + (size_t)t * NHh + (size_t)(nb0 + rr) * HH + (c0 + rc);
        const float x_pre = __ldcg(outp);   // pre-activation, prefetched early

        unsigned long long acc[8];
#pragma unroll
        for (int j = 0; j < 8; j++) acc[j] = 0ull;

        float cur[8], nxt[8];
#pragma unroll
        for (int j = 0; j < 8; j++) cur[j] = __ldcg(hp + (size_t)j * NB);

#pragma unroll
        for (int g = 0; g < 8; g++) {
            if (g < 7) {
#pragma unroll
                for (int j = 0; j < 8; j++)
                    nxt[j] = __ldcg(hp + (size_t)((g + 1) * 8 + j) * NB);
            }
#pragma unroll
            for (int j = 0; j < 8; j++) {
                const unsigned long long ad = dup2(cur[j]);
                const float* wk = &Whs[(k0 + g * 8 + j) * 16];
                ulonglong2 w0 = *(const ulonglong2*)(wk + 0);
                ulonglong2 w1 = *(const ulonglong2*)(wk + 4);
                ulonglong2 w2 = *(const ulonglong2*)(wk + 8);
                ulonglong2 w3 = *(const ulonglong2*)(wk + 12);
                fma2(acc[0], ad, w0.x); fma2(acc[1], ad, w0.y);
                fma2(acc[2], ad, w1.x); fma2(acc[3], ad, w1.y);
                fma2(acc[4], ad, w2.x); fma2(acc[5], ad, w2.y);
                fma2(acc[6], ad, w3.x); fma2(acc[7], ad, w3.y);
            }
            if (g < 7) {
#pragma unroll
                for (int j = 0; j < 8; j++) cur[j] = nxt[j];
            }
        }

        // partials -> redU[wid][lane][0..7]
        {
            unsigned long long* rp = &redU[(size_t)(wid * 32 + lane) * 9];
#pragma unroll
            for (int j = 0; j < 8; j++) rp[j] = acc[j];
        }
        __syncthreads();   // A

        // reduce 16 k-chunks for output (n=rr, c=rc)
        float s = 0.0f;
#pragma unroll
        for (int w = 0; w < 16; w++)
            s += redF[((w * 32 + rr) * 9 + (rc >> 1)) * 2 + (rc & 1)];
        const float v = retanh(s + x_pre);
        *outp = v;                       // [T,N,H] store for downstream GEMM
        sv[rc * 33 + rr] = v;            // stage transpose
        __syncthreads();   // B

        // coalesced publish to hx ([H][N] layout)
        hn[(size_t)(c0 + c2) * NB + nb0 + n2] = sv[c2 * 33 + n2];
        __syncthreads();   // C

        // ---- two-level per-half grid barrier (counters start at 0) ----
        if (tid == 0) {
            const unsigned a = atom_add_acqrel(&g_grpc[gid * 32], 1u);
            if (a == (unsigned)(t * 16 + 15))              // 16th arrival this step
                red_add_release(&g_epc[bidb * 32], 1u);
            const unsigned tgt = (unsigned)((t + 1) * 4);  // 4 group leaders/half
            while (ld_acquire(&g_epc[bidb * 32]) < tgt) __nanosleep(20);
        }
        __syncthreads();   // D
    }
}

// ======================= launcher ==============================================
static void launch_gemm(const float* A, const float* B, const float* b1,
                        const float* b2, float* C, int M, int Nc, int K,
                        int D1, int D2, int act)
{
    dim3 grid(Nc / BN, M / BM);
    sgemm_kernel<<<grid, 256>>>(A, B, b1, b2, C, M, Nc, K, D1, D2, act);
}

extern "C" void kernel_launch(void* const* d_in, const int* in_sizes, int n_in,
                              void* d_out, int out_size)
{
    const float* data = (const float*)d_in[0];
    const float* h0_v = (const float*)d_in[1];
    const float* h0_m = (const float*)d_in[2];
    const float* Wi   = (const float*)d_in[3];
    const float* bi   = (const float*)d_in[4];
    const float* Wh   = (const float*)d_in[5];
    const float* bh   = (const float*)d_in[6];
    const float* Wo   = (const float*)d_in[7];
    const float* bo   = (const float*)d_in[8];
    const float* Wt   = (const float*)d_in[9];
    const float* bt   = (const float*)d_in[10];
    const float* Wi2  = (const float*)d_in[11];
    const float* bi2  = (const float*)d_in[12];
    const float* Wh2  = (const float*)d_in[13];
    const float* bh2  = (const float*)d_in[14];
    const float* Wo2  = (const float*)d_in[15];
    const float* bo2  = (const float*)d_in[16];
    float* out = (float*)d_out;

    float *bufA, *bufB, *bufO, *bufO2, *hx0, *hx1;
    cudaGetSymbolAddress((void**)&bufA,  g_bufA);
    cudaGetSymbolAddress((void**)&bufB,  g_bufB);
    cudaGetSymbolAddress((void**)&bufO,  g_bufO);
    cudaGetSymbolAddress((void**)&bufO2, g_bufO2);
    cudaGetSymbolAddress((void**)&hx0,   g_hx0);
    cudaGetSymbolAddress((void**)&hx1,   g_hx1);

    cudaFuncSetAttribute(recur_kernel,
                         cudaFuncAttributeMaxDynamicSharedMemorySize, RSMEM);

    // 1) inp_v = data @ Wi^T + (bi + bh) -> [T,N,H]
    launch_gemm(data, Wi, bi, bh, bufA, NT, HH, II, TT, NB, 0);
    // 2) visual recurrence
    transpose_h0<<<128, 512>>>(h0_v, hx0);
    reset_barrier_kernel<<<1, 256>>>();
    recur_kernel<<<RGRID, RTHR, RSMEM>>>(bufA, Wh, hx0, hx1);
    // 3) out_v = hs_v @ Wo^T + bo -> [N,T,O]
    launch_gemm(bufA, Wo, bo, nullptr, bufO, NT, OO, HH, NB, TT, 0);
    // 4) out_t = retanh(out_v @ Wt^T + bt)
    launch_gemm(bufO, Wt, bt, nullptr, bufO2, NT, OO, OO, NT, 1, 1);
    // 5) inp_m = out_t @ Wi2^T + (bi2 + bh2) -> [T,N,H]
    launch_gemm(bufO2, Wi2, bi2, bh2, bufB, NT, HH, OO, TT, NB, 0);
    // 6) motor recurrence
    transpose_h0<<<128, 512>>>(h0_m, hx0);
    reset_barrier_kernel<<<1, 256>>>();
    recur_kernel<<<RGRID, RTHR, RSMEM>>>(bufB, Wh2, hx0, hx1);
    // 7) out_m = hs_m @ Wo2^T + bo2 -> [N,T,O]
    launch_gemm(bufB, Wo2, bo2, nullptr, out, NT, OO, HH, NB, TT, 0);
}

// round 5
// speedup vs baseline: 3.6247x; 1.1045x over previous
#include <cuda_runtime.h>
#include <cuda_bf16.h>

// Problem dims
#define NB 64
#define TT 512
#define II 512
#define HH 1024
#define OO 512
#define NT (NB*TT)        // 32768
#define NHh (NB*HH)       // 65536 floats per timestep slab

// ---------------- scratch (device globals; no cudaMalloc allowed) -------------
__device__ float g_bufA[TT*NB*HH];   // 128 MB : inp_v -> hs_v (in-place)
__device__ float g_bufB[TT*NB*HH];   // 128 MB : inp_m -> hs_m (in-place)
__device__ float g_bufO[NT*OO];      //  64 MB : out_v
__device__ float g_bufO2[NT*OO];     //  64 MB : out_t
__device__ float g_hx0[HH*NB];       // ping-pong h exchange, [H][N] layout
__device__ float g_hx1[HH*NB];
// producer-consumer flags: [half 0..1][group 0..15], padded by 32 uints
__device__ unsigned g_gflag[32*32];

// ---------------- packed fp32x2 helpers (Blackwell dual-FP32 pipe) ------------
__device__ __forceinline__ unsigned long long dup2(float a) {
    unsigned long long r;
    asm("mov.b64 %0, {%1, %1};" : "=l"(r) : "f"(a));
    return r;
}
__device__ __forceinline__ void fma2(unsigned long long& c, unsigned long long a,
                                     unsigned long long b) {
    asm("fma.rn.f32x2 %0, %1, %2, %0;" : "+l"(c) : "l"(a), "l"(b));
}
__device__ __forceinline__ float lo32(unsigned long long v) {
    return __uint_as_float((unsigned)(v & 0xffffffffull));
}
__device__ __forceinline__ float hi32(unsigned long long v) {
    return __uint_as_float((unsigned)(v >> 32));
}
__device__ __forceinline__ unsigned ld_acquire(const unsigned* p) {
    unsigned v;
    asm volatile("ld.acquire.gpu.global.u32 %0, [%1];" : "=r"(v) : "l"(p));
    return v;
}
__device__ __forceinline__ void red_add_release(unsigned* p, unsigned v) {
    asm volatile("red.add.release.gpu.global.u32 [%0], %1;" :: "l"(p), "r"(v));
}
__device__ __forceinline__ float retanh(float x) { return tanhf(fmaxf(x, 0.0f)); }

// ======================= SGEMM: C[remap(m)][:] = A[m,:K] @ B[:,K]^T + bias ====
// Register-prefetch pipelined: next tile's LDGs overlap current tile's FMAs.
#define BM 128
#define BN 128
#define BK 16

__global__ __launch_bounds__(256, 2) void sgemm_kernel(
    const float* __restrict__ A, const float* __restrict__ B,
    const float* __restrict__ bias1, const float* __restrict__ bias2,
    float* __restrict__ C, int M, int Nc, int K, int D1, int D2, int act)
{
    __shared__ float As[BK][BM + 8];
    __shared__ float Bs[BK][BN + 8];

    const int tid = threadIdx.x;
    const int m0 = blockIdx.y * BM;
    const int j0 = blockIdx.x * BN;
    const int tm = tid >> 4;
    const int tn = tid & 15;
    const int lr = tid >> 2;
    const int lk = (tid & 3) * 4;

    const float* ap0 = A + (size_t)(m0 + lr) * K + lk;
    const float* ap1 = A + (size_t)(m0 + lr + 64) * K + lk;
    const float* bp0 = B + (size_t)(j0 + lr) * K + lk;
    const float* bp1 = B + (size_t)(j0 + lr + 64) * K + lk;

    unsigned long long acc[8][4];
#pragma unroll
    for (int i = 0; i < 8; i++)
#pragma unroll
        for (int j = 0; j < 4; j++) acc[i][j] = 0ull;

    float4 pa0 = *(const float4*)ap0;
    float4 pa1 = *(const float4*)ap1;
    float4 pb0 = *(const float4*)bp0;
    float4 pb1 = *(const float4*)bp1;

    for (int kt = 0; kt < K; kt += BK) {
        As[lk + 0][lr] = pa0.x; As[lk + 1][lr] = pa0.y;
        As[lk + 2][lr] = pa0.z; As[lk + 3][lr] = pa0.w;
        As[lk + 0][lr + 64] = pa1.x; As[lk + 1][lr + 64] = pa1.y;
        As[lk + 2][lr + 64] = pa1.z; As[lk + 3][lr + 64] = pa1.w;
        Bs[lk + 0][lr] = pb0.x; Bs[lk + 1][lr] = pb0.y;
        Bs[lk + 2][lr] = pb0.z; Bs[lk + 3][lr] = pb0.w;
        Bs[lk + 0][lr + 64] = pb1.x; Bs[lk + 1][lr + 64] = pb1.y;
        Bs[lk + 2][lr + 64] = pb1.z; Bs[lk + 3][lr + 64] = pb1.w;
        __syncthreads();

        if (kt + BK < K) {   // next tile's LDGs fly during compute
            pa0 = *(const float4*)(ap0 + kt + BK);
            pa1 = *(const float4*)(ap1 + kt + BK);
            pb0 = *(const float4*)(bp0 + kt + BK);
            pb1 = *(const float4*)(bp1 + kt + BK);
        }

#pragma unroll
        for (int kk = 0; kk < BK; kk++) {
            float a[8];
            *(float4*)&a[0] = *(const float4*)&As[kk][tm * 8];
            *(float4*)&a[4] = *(const float4*)&As[kk][tm * 8 + 4];
            ulonglong2 b01 = *(const ulonglong2*)&Bs[kk][tn * 8];
            ulonglong2 b23 = *(const ulonglong2*)&Bs[kk][tn * 8 + 4];
#pragma unroll
            for (int i = 0; i < 8; i++) {
                unsigned long long ad = dup2(a[i]);
                fma2(acc[i][0], ad, b01.x);
                fma2(acc[i][1], ad, b01.y);
                fma2(acc[i][2], ad, b23.x);
                fma2(acc[i][3], ad, b23.y);
            }
        }
        __syncthreads();
    }

    float bcol[8];
#pragma unroll
    for (int j = 0; j < 8; j++) {
        const int cn = j0 + tn * 8 + j;
        float b = bias1[cn];
        if (bias2) b += bias2[cn];
        bcol[j] = b;
    }
#pragma unroll
    for (int i = 0; i < 8; i++) {
        const int rm = m0 + tm * 8 + i;
        const int orow = (rm % D1) * D2 + (rm / D1);
        float out[8];
#pragma unroll
        for (int j = 0; j < 4; j++) {
            out[2 * j + 0] = lo32(acc[i][j]) + bcol[2 * j + 0];
            out[2 * j + 1] = hi32(acc[i][j]) + bcol[2 * j + 1];
        }
        if (act) {
#pragma unroll
            for (int j = 0; j < 8; j++) out[j] = retanh(out[j]);
        }
        float* cp = C + (size_t)orow * Nc + j0 + tn * 8;
        *(float4*)cp       = *(float4*)&out[0];
        *(float4*)(cp + 4) = *(float4*)&out[4];
    }
}

// ======================= h0 transpose + flag reset ===========================
__global__ __launch_bounds__(512) void transpose_h0(
    const float* __restrict__ h0, float* __restrict__ hx)
{
    const int idx = blockIdx.x * 512 + threadIdx.x;
    const int h = idx >> 6, n = idx & 63;
    hx[idx] = h0[(size_t)n * HH + h];
}

__global__ __launch_bounds__(1024) void reset_flags_kernel() {
    g_gflag[threadIdx.x] = 0u;
}

// ======================= Persistent recurrence kernel =========================
// Grid = 128 CTAs = 2 batch halves x 64 column-slices of 16.
// 16 warps each own a 64-wide k-chunk (= slice group wid), compute all 16
// columns via f32x2. Fine-grained producer-consumer flags replace the grid
// barrier: warp wid waits only for its 4 source slices' publishes.
#define RGRID 128
#define RTHR  512
// Whs 1024*16 f (64KB) + redU 4608 ull = 9216 f (36KB) + sv 16*33 f (2112B)
#define RSMEM ((16384 + 9216 + 528) * 4)

__global__ __launch_bounds__(RTHR) void recur_kernel(
    float* __restrict__ buf, const float* __restrict__ Wh,
    float* __restrict__ hx0, float* __restrict__ hx1)
{
    extern __shared__ float smem[];
    float* Whs = smem;                                                // [1024][16]
    unsigned long long* redU = (unsigned long long*)(smem + 16384);   // [16][32][9]
    float* sv = smem + 16384 + 9216;                                  // [16][33]

    const int tid  = threadIdx.x;
    const int bidb = blockIdx.x >> 6;     // batch half
    const int bidh = blockIdx.x & 63;     // column slice
    const int nb0  = bidb * 32;
    const int c0   = bidh * 16;

    // Wh slice transposed into SMEM: Whs[k][cl] = Wh[c0+cl][k]
    {
        const int cl = tid & 15;
        const int kb = (tid >> 4) * 32;
        const float* wrow = Wh + (size_t)(c0 + cl) * HH + kb;
#pragma unroll
        for (int kk = 0; kk < 32; kk++) Whs[(kb + kk) * 16 + cl] = wrow[kk];
    }
    __syncthreads();

    const int wid  = tid >> 5;            // k-chunk / flag group 0..15
    const int lane = tid & 31;            // batch row within half
    const int k0   = wid * 64;
    const int rr   = tid >> 4;            // reduce: n 0..31
    const int rc   = tid & 15;            // reduce: c 0..15
    const int c2   = tid >> 5;            // publish: c 0..15
    const int n2   = tid & 31;            // publish: n 0..31
    const float* redF = (const float*)redU;

    const unsigned* my_wait_flag = &g_gflag[(bidb * 16 + wid) * 32];
    unsigned* my_post_flag = &g_gflag[(bidb * 16 + (bidh >> 2)) * 32];

    for (int t = 0; t < TT; t++) {
        const float* hp = ((t & 1) ? hx1 : hx0) + (size_t)k0 * NB + nb0 + lane;
        float*       hn = ((t & 1) ? hx0 : hx1);
        float* outp = buf + (size_t)t * NHh + (size_t)(nb0 + rr) * HH + (c0 + rc);
        const float x_pre = __ldcg(outp);   // step-independent: load before wait

        // wait until my 4 source slices have published step t-1 (counter = 4t)
        {
            const unsigned tgt = 4u * (unsigned)t;
            while (ld_acquire(my_wait_flag) < tgt) __nanosleep(20);
        }

        unsigned long long acc[8];
#pragma unroll
        for (int j = 0; j < 8; j++) acc[j] = 0ull;

        // software pipeline, prefetch distance 2 (3-deep rolling buffer)
        float hbuf[3][8];
#pragma unroll
        for (int j = 0; j < 8; j++) hbuf[0][j] = __ldcg(hp + (size_t)j * NB);
#pragma unroll
        for (int j = 0; j < 8; j++) hbuf[1][j] = __ldcg(hp + (size_t)(8 + j) * NB);

#pragma unroll
        for (int g = 0; g < 8; g++) {
            if (g + 2 < 8) {
#pragma unroll
                for (int j = 0; j < 8; j++)
                    hbuf[(g + 2) % 3][j] =
                        __ldcg(hp + (size_t)((g + 2) * 8 + j) * NB);
            }
#pragma unroll
            for (int j = 0; j < 8; j++) {
                const unsigned long long ad = dup2(hbuf[g % 3][j]);
                const float* wk = &Whs[(k0 + g * 8 + j) * 16];
                ulonglong2 w0 = *(const ulonglong2*)(wk + 0);
                ulonglong2 w1 = *(const ulonglong2*)(wk + 4);
                ulonglong2 w2 = *(const ulonglong2*)(wk + 8);
                ulonglong2 w3 = *(const ulonglong2*)(wk + 12);
                fma2(acc[0], ad, w0.x); fma2(acc[1], ad, w0.y);
                fma2(acc[2], ad, w1.x); fma2(acc[3], ad, w1.y);
                fma2(acc[4], ad, w2.x); fma2(acc[5], ad, w2.y);
                fma2(acc[6], ad, w3.x); fma2(acc[7], ad, w3.y);
            }
        }

        // partials -> redU[wid][lane][0..7]
        {
            unsigned long long* rp = &redU[(size_t)(wid * 32 + lane) * 9];
#pragma unroll
            for (int j = 0; j < 8; j++) rp[j] = acc[j];
        }
        __syncthreads();   // A

        // reduce 16 k-chunks for output (n=rr, c=rc)
        float s = 0.0f;
#pragma unroll
        for (int w = 0; w < 16; w++)
            s += redF[((w * 32 + rr) * 9 + (rc >> 1)) * 2 + (rc & 1)];
        const float v = retanh(s + x_pre);
        *outp = v;                       // [T,N,H] store for downstream GEMM
        sv[rc * 33 + rr] = v;            // stage transpose
        __syncthreads();   // B

        // coalesced publish to hx ([H][N] layout)
        hn[(size_t)(c0 + c2) * NB + nb0 + n2] = sv[c2 * 33 + n2];
        __syncthreads();   // C

        // announce: this slice published step t (+1 to my group's counter)
        if (tid == 0) red_add_release(my_post_flag, 1u);
    }
}

// ======================= launcher ==============================================
static void launch_gemm(const float* A, const float* B, const float* b1,
                        const float* b2, float* C, int M, int Nc, int K,
                        int D1, int D2, int act)
{
    dim3 grid(Nc / BN, M / BM);
    sgemm_kernel<<<grid, 256>>>(A, B, b1, b2, C, M, Nc, K, D1, D2, act);
}

extern "C" void kernel_launch(void* const* d_in, const int* in_sizes, int n_in,
                              void* d_out, int out_size)
{
    const float* data = (const float*)d_in[0];
    const float* h0_v = (const float*)d_in[1];
    const float* h0_m = (const float*)d_in[2];
    const float* Wi   = (const float*)d_in[3];
    const float* bi   = (const float*)d_in[4];
    const float* Wh   = (const float*)d_in[5];
    const float* bh   = (const float*)d_in[6];
    const float* Wo   = (const float*)d_in[7];
    const float* bo   = (const float*)d_in[8];
    const float* Wt   = (const float*)d_in[9];
    const float* bt   = (const float*)d_in[10];
    const float* Wi2  = (const float*)d_in[11];
    const float* bi2  = (const float*)d_in[12];
    const float* Wh2  = (const float*)d_in[13];
    const float* bh2  = (const float*)d_in[14];
    const float* Wo2  = (const float*)d_in[15];
    const float* bo2  = (const float*)d_in[16];
    float* out = (float*)d_out;

    float *bufA, *bufB, *bufO, *bufO2, *hx0, *hx1;
    cudaGetSymbolAddress((void**)&bufA,  g_bufA);
    cudaGetSymbolAddress((void**)&bufB,  g_bufB);
    cudaGetSymbolAddress((void**)&bufO,  g_bufO);
    cudaGetSymbolAddress((void**)&bufO2, g_bufO2);
    cudaGetSymbolAddress((void**)&hx0,   g_hx0);
    cudaGetSymbolAddress((void**)&hx1,   g_hx1);

    cudaFuncSetAttribute(recur_kernel,
                         cudaFuncAttributeMaxDynamicSharedMemorySize, RSMEM);

    // 1) inp_v = data @ Wi^T + (bi + bh) -> [T,N,H]
    launch_gemm(data, Wi, bi, bh, bufA, NT, HH, II, TT, NB, 0);
    // 2) visual recurrence
    transpose_h0<<<128, 512>>>(h0_v, hx0);
    reset_flags_kernel<<<1, 1024>>>();
    recur_kernel<<<RGRID, RTHR, RSMEM>>>(bufA, Wh, hx0, hx1);
    // 3) out_v = hs_v @ Wo^T + bo -> [N,T,O]
    launch_gemm(bufA, Wo, bo, nullptr, bufO, NT, OO, HH, NB, TT, 0);
    // 4) out_t = retanh(out_v @ Wt^T + bt)
    launch_gemm(bufO, Wt, bt, nullptr, bufO2, NT, OO, OO, NT, 1, 1);
    // 5) inp_m = out_t @ Wi2^T + (bi2 + bh2) -> [T,N,H]
    launch_gemm(bufO2, Wi2, bi2, bh2, bufB, NT, HH, OO, TT, NB, 0);
    // 6) motor recurrence
    transpose_h0<<<128, 512>>>(h0_m, hx0);
    reset_flags_kernel<<<1, 1024>>>();
    recur_kernel<<<RGRID, RTHR, RSMEM>>>(bufB, Wh2, hx0, hx1);
    // 7) out_m = hs_m @ Wo2^T + bo2 -> [N,T,O]
    launch_gemm(bufB, Wo2, bo2, nullptr, out, NT, OO, HH, NB, TT, 0);
}